// round 12
// baseline (speedup 1.0000x reference)
#include <cuda_runtime.h>
#include <cuda_bf16.h>
#include <math.h>

// Problem constants
#define N_TOK   32768      // 32 * 32 * 32
#define N_E     1024
#define E_DIM   64
#define N_ELEM  2097152    // 32*64*32*32
#define HW      1024
#define BETA    0.25f
#define DECAY   0.99f
#define EPSF    1e-5f

// Output layout (flattened reference tuple, float32)
#define O_LOSS   0
#define O_ZQ     1
#define O_PERP   (1 + N_ELEM)
#define O_MINENC (2 + N_ELEM)
#define O_IDX    (2 + N_ELEM + (size_t)N_TOK*N_E)

// Scratch (no allocations allowed -> device globals)
__device__ int   g_idx[N_TOK];
__device__ float g_enorm[N_E];
__device__ float g_cs[N_E];
__device__ float g_csn[N_E];
__device__ float g_sum[N_E * E_DIM];
__device__ float g_emb[N_E * E_DIM];
__device__ float g_loss_acc;
__device__ unsigned int g_done;

// ---- packed f32x2 helpers (semantics identical to 2x scalar FFMA per lane) ----
#define FMA2(d, a, b, c) \
    asm("fma.rn.f32x2 %0, %1, %2, %3;" : "=l"(d) : "l"(a), "l"(b), "l"(c))
#define UNPACK2(lo, hi, v) \
    asm("mov.b64 {%0, %1}, %2;" : "=f"(lo), "=f"(hi) : "l"(v))
#define PACK2(v, lo, hi) \
    asm("mov.b64 %0, {%1, %2};" : "=l"(v) : "f"(lo), "f"(hi))
#define LDSV2(e01, e23, base, OFF) \
    asm("ld.shared.v2.u64 {%0, %1}, [%2+" #OFF "];" \
        : "=l"(e01), "=l"(e23) : "r"(base))

// ---------------------------------------------------------------------------
// Kernel 0: codebook norms + zero scratch
// ---------------------------------------------------------------------------
__global__ void k_prep(const float* __restrict__ emb) {
    int j = blockIdx.x * 256 + threadIdx.x;
    if (j < N_E) {
        const float* e = emb + j * E_DIM;
        float s0 = 0.f, s1 = 0.f, s2 = 0.f, s3 = 0.f;
        #pragma unroll
        for (int c = 0; c < E_DIM; c += 4) {
            s0 = __fmaf_rn(e[c+0], e[c+0], s0);
            s1 = __fmaf_rn(e[c+1], e[c+1], s1);
            s2 = __fmaf_rn(e[c+2], e[c+2], s2);
            s3 = __fmaf_rn(e[c+3], e[c+3], s3);
        }
        g_enorm[j] = __fadd_rn(__fadd_rn(s0, s1), __fadd_rn(s2, s3));
        g_cs[j] = 0.f;
        float4 z4 = make_float4(0.f, 0.f, 0.f, 0.f);
        float4* s = reinterpret_cast<float4*>(g_sum + j * E_DIM);
        #pragma unroll
        for (int c = 0; c < E_DIM / 4; ++c) s[c] = z4;
        if (j == 0) { g_loss_acc = 0.f; g_done = 0u; }
    }
}

// ---------------------------------------------------------------------------
// Kernel 1: per-token argmin (math bit-identical to the 231.5us kernel).
// Occupancy raised to 3 CTAs/SM (12 warps/SM) to fill the FMA pipe.
// blk0 offsets the block index so the kernel can be launched in halves.
// ---------------------------------------------------------------------------
#define ST 68

__global__ __launch_bounds__(128, 3)
void k_argmin(const float* __restrict__ z,
              const float* __restrict__ emb,
              float* __restrict__ out,
              int blk0) {
    __shared__ __align__(16) float tile[64 * ST];
    __shared__ float sn[64];

    const int t   = threadIdx.x;
    const int n0  = (blockIdx.x + blk0) * 128;
    const int b   = n0 >> 10;
    const int hw0 = n0 & 1023;
    const float* zb = z + (size_t)b * E_DIM * HW;

    float4 zr[16];
    #pragma unroll
    for (int g = 0; g < 2; ++g) {
        __syncthreads();
        #pragma unroll
        for (int k = 0; k < 32; ++k) {
            int c = k * 2 + (t >> 6);
            int i = t & 63;
            tile[i * ST + c] = zb[c * HW + hw0 + g * 64 + i];
        }
        __syncthreads();
        if ((t >> 6) == g) {
            int local = t & 63;
            #pragma unroll
            for (int q = 0; q < 16; ++q)
                zr[q] = *reinterpret_cast<const float4*>(&tile[local * ST + 4 * q]);
        }
    }

    unsigned long long zp[32];
    #pragma unroll
    for (int q = 0; q < 16; ++q) {
        PACK2(zp[2*q+0], zr[q].x, zr[q].y);
        PACK2(zp[2*q+1], zr[q].z, zr[q].w);
    }

    float zn;
    {
        unsigned long long na = 0ull, nb = 0ull;
        #pragma unroll
        for (int q = 0; q < 16; ++q) {
            FMA2(na, zp[2*q+0], zp[2*q+0], na);
            FMA2(nb, zp[2*q+1], zp[2*q+1], nb);
        }
        float a0, a1, a2, a3;
        UNPACK2(a0, a1, na);
        UNPACK2(a2, a3, nb);
        zn = __fadd_rn(__fadd_rn(a0, a1), __fadd_rn(a2, a3));
    }

    float best = 3.4e38f;
    int bestIdx = 0;
    const unsigned tbase = (unsigned)__cvta_generic_to_shared(tile);

    for (int tile0 = 0; tile0 < N_E; tile0 += 64) {
        __syncthreads();
        #pragma unroll
        for (int k = 0; k < 32; ++k) {
            int j = k * 2 + (t >> 6);
            int c = t & 63;
            tile[j * ST + c] = emb[(tile0 + j) * E_DIM + c];
        }
        if (t < 64) sn[t] = g_enorm[tile0 + t];
        __syncthreads();

        #pragma unroll 4
        for (int j = 0; j < 64; ++j) {
            const unsigned rowa = tbase + (unsigned)(j * (ST * 4));
            unsigned long long acc_a = 0ull, acc_b = 0ull;
            unsigned long long e01, e23;
            LDSV2(e01, e23, rowa,   0); FMA2(acc_a, zp[ 0], e01, acc_a); FMA2(acc_b, zp[ 1], e23, acc_b);
            LDSV2(e01, e23, rowa,  16); FMA2(acc_a, zp[ 2], e01, acc_a); FMA2(acc_b, zp[ 3], e23, acc_b);
            LDSV2(e01, e23, rowa,  32); FMA2(acc_a, zp[ 4], e01, acc_a); FMA2(acc_b, zp[ 5], e23, acc_b);
            LDSV2(e01, e23, rowa,  48); FMA2(acc_a, zp[ 6], e01, acc_a); FMA2(acc_b, zp[ 7], e23, acc_b);
            LDSV2(e01, e23, rowa,  64); FMA2(acc_a, zp[ 8], e01, acc_a); FMA2(acc_b, zp[ 9], e23, acc_b);
            LDSV2(e01, e23, rowa,  80); FMA2(acc_a, zp[10], e01, acc_a); FMA2(acc_b, zp[11], e23, acc_b);
            LDSV2(e01, e23, rowa,  96); FMA2(acc_a, zp[12], e01, acc_a); FMA2(acc_b, zp[13], e23, acc_b);
            LDSV2(e01, e23, rowa, 112); FMA2(acc_a, zp[14], e01, acc_a); FMA2(acc_b, zp[15], e23, acc_b);
            LDSV2(e01, e23, rowa, 128); FMA2(acc_a, zp[16], e01, acc_a); FMA2(acc_b, zp[17], e23, acc_b);
            LDSV2(e01, e23, rowa, 144); FMA2(acc_a, zp[18], e01, acc_a); FMA2(acc_b, zp[19], e23, acc_b);
            LDSV2(e01, e23, rowa, 160); FMA2(acc_a, zp[20], e01, acc_a); FMA2(acc_b, zp[21], e23, acc_b);
            LDSV2(e01, e23, rowa, 176); FMA2(acc_a, zp[22], e01, acc_a); FMA2(acc_b, zp[23], e23, acc_b);
            LDSV2(e01, e23, rowa, 192); FMA2(acc_a, zp[24], e01, acc_a); FMA2(acc_b, zp[25], e23, acc_b);
            LDSV2(e01, e23, rowa, 208); FMA2(acc_a, zp[26], e01, acc_a); FMA2(acc_b, zp[27], e23, acc_b);
            LDSV2(e01, e23, rowa, 224); FMA2(acc_a, zp[28], e01, acc_a); FMA2(acc_b, zp[29], e23, acc_b);
            LDSV2(e01, e23, rowa, 240); FMA2(acc_a, zp[30], e01, acc_a); FMA2(acc_b, zp[31], e23, acc_b);

            float d0, d1, d2, d3;
            UNPACK2(d0, d1, acc_a);
            UNPACK2(d2, d3, acc_b);
            float dot = __fadd_rn(__fadd_rn(d0, d1), __fadd_rn(d2, d3));
            float dval = __fadd_rn(__fadd_rn(zn, sn[j]), -__fmul_rn(2.0f, dot));
            if (dval < best) { best = dval; bestIdx = tile0 + j; }
        }
    }

    const int n = n0 + t;
    g_idx[n] = bestIdx;
    out[O_IDX + n] = (float)bestIdx;

    atomicAdd(&g_cs[bestIdx], 1.0f);
    float* s = g_sum + bestIdx * E_DIM;
    #pragma unroll
    for (int q = 0; q < 32; ++q) {
        float lo, hi;
        UNPACK2(lo, hi, zp[q]);
        atomicAdd(&s[2*q+0], lo);
        atomicAdd(&s[2*q+1], hi);
    }
}

// ---------------------------------------------------------------------------
// Kernel 2: coalesced one-hot for a half of the tokens (overlaps argmin of the
// other half on the side stream)
// ---------------------------------------------------------------------------
__global__ __launch_bounds__(256)
void k_onehot(float* __restrict__ out, int tok0) {
    int i = blockIdx.x * 256 + threadIdx.x;       // float2 index within half
    int n = tok0 + (i >> 9);
    int c = (i & 511) << 1;
    int idx = g_idx[n];
    float2 v;
    v.x = (c     == idx) ? 1.0f : 0.0f;
    v.y = (c + 1 == idx) ? 1.0f : 0.0f;
    reinterpret_cast<float2*>(out + O_MINENC)[(size_t)tok0 * 512 + i] = v;
}

// ---------------------------------------------------------------------------
// Kernel 3: EMA cluster-size stats + normalizer + perplexity
// ---------------------------------------------------------------------------
__global__ void k_stats(const float* __restrict__ ema_cs,
                        float* __restrict__ out) {
    __shared__ float red[1024];
    const int j = threadIdx.x;
    const float KD = (float)(1.0 - 0.99);

    float cs  = g_cs[j];
    float ncs = __fadd_rn(__fmul_rn(DECAY, ema_cs[j]), __fmul_rn(KD, cs));

    red[j] = ncs;
    __syncthreads();
    for (int s = 512; s > 0; s >>= 1) {
        if (j < s) red[j] = __fadd_rn(red[j], red[j + s]);
        __syncthreads();
    }
    float nsum = red[0];
    __syncthreads();

    g_csn[j] = __fmul_rn(__fdiv_rn(__fadd_rn(ncs, EPSF),
                                   __fadd_rn(nsum, (float)N_E * EPSF)), nsum);

    float avg = cs * (1.0f / (float)N_TOK);
    float pt  = __fmul_rn(avg, logf(__fadd_rn(avg, 1e-10f)));
    red[j] = pt;
    __syncthreads();
    for (int s = 512; s > 0; s >>= 1) {
        if (j < s) red[j] = __fadd_rn(red[j], red[j + s]);
        __syncthreads();
    }
    if (j == 0) out[O_PERP] = expf(-red[0]);
}

// ---------------------------------------------------------------------------
// Kernel 4: parallel codebook EMA update
// ---------------------------------------------------------------------------
__global__ void k_emb(const float* __restrict__ ema_w) {
    const float KD = (float)(1.0 - 0.99);
    int i = blockIdx.x * 256 + threadIdx.x;
    if (i < N_E * E_DIM) {
        int j = i >> 6;
        float nw = __fadd_rn(__fmul_rn(DECAY, ema_w[i]),
                             __fmul_rn(KD, g_sum[i]));
        g_emb[i] = __fdiv_rn(nw, g_csn[j]);
    }
}

// ---------------------------------------------------------------------------
// Kernel 5: z_q gather + straight-through + loss (last block finalizes loss)
// ---------------------------------------------------------------------------
#define ZQ_BLOCKS (N_ELEM / 256)

__global__ void k_zq(const float* __restrict__ z, float* __restrict__ out) {
    __shared__ float warpsum[8];
    int i = blockIdx.x * 256 + threadIdx.x;
    float acc = 0.f;
    if (i < N_ELEM) {
        int hw = i & 1023;
        int c  = (i >> 10) & 63;
        int b  = i >> 16;
        int n  = (b << 10) | hw;
        float q  = g_emb[g_idx[n] * E_DIM + c];
        float zv = z[i];
        float dq = __fsub_rn(q, zv);
        out[O_ZQ + i] = __fadd_rn(zv, dq);
        acc = __fmul_rn(dq, dq);
    }
    #pragma unroll
    for (int s = 16; s > 0; s >>= 1)
        acc += __shfl_down_sync(0xffffffffu, acc, s);
    int lane = threadIdx.x & 31, wid = threadIdx.x >> 5;
    if (lane == 0) warpsum[wid] = acc;
    __syncthreads();
    if (wid == 0) {
        float v = (lane < 8) ? warpsum[lane] : 0.f;
        #pragma unroll
        for (int s = 4; s > 0; s >>= 1)
            v += __shfl_down_sync(0xffffffffu, v, s);
        if (lane == 0) {
            atomicAdd(&g_loss_acc, v);
            __threadfence();
            unsigned int done = atomicAdd(&g_done, 1u);
            if (done == ZQ_BLOCKS - 1) {
                out[O_LOSS] = __fmul_rn(BETA,
                                        __fdiv_rn(g_loss_acc, (float)N_ELEM));
            }
        }
    }
}

// ---------------------------------------------------------------------------
// Side stream for graph-forked overlap (created at static-init time)
// ---------------------------------------------------------------------------
namespace {
struct SideStream {
    cudaStream_t s2 = nullptr;
    cudaEvent_t evA = nullptr, evB = nullptr, evJ = nullptr;
    SideStream() {
        if (cudaStreamCreateWithFlags(&s2, cudaStreamNonBlocking) != cudaSuccess) {
            s2 = nullptr;
            return;
        }
        if (cudaEventCreateWithFlags(&evA, cudaEventDisableTiming) != cudaSuccess ||
            cudaEventCreateWithFlags(&evB, cudaEventDisableTiming) != cudaSuccess ||
            cudaEventCreateWithFlags(&evJ, cudaEventDisableTiming) != cudaSuccess) {
            s2 = nullptr;
        }
    }
};
SideStream g_ss;
}

#define HALF_BLOCKS (N_TOK / 128 / 2)              // 128 argmin blocks per half
#define OH_HALF_BLOCKS ((N_TOK / 2) * 512 / 256)   // 32768 onehot blocks per half

// ---------------------------------------------------------------------------
extern "C" void kernel_launch(void* const* d_in, const int* in_sizes, int n_in,
                              void* d_out, int out_size) {
    const float* z      = (const float*)d_in[0];
    const float* emb_w  = (const float*)d_in[1];
    const float* ema_cs = (const float*)d_in[2];
    const float* ema_w  = (const float*)d_in[3];
    float* out = (float*)d_out;

    k_prep<<<(N_E + 255) / 256, 256>>>(emb_w);

    if (g_ss.s2) {
        // half 0 argmin, then fork: onehot(half0) on s2 overlaps argmin(half1)
        k_argmin<<<HALF_BLOCKS, 128>>>(z, emb_w, out, 0);
        cudaEventRecord(g_ss.evA, 0);
        cudaStreamWaitEvent(g_ss.s2, g_ss.evA, 0);
        k_onehot<<<OH_HALF_BLOCKS, 256, 0, g_ss.s2>>>(out, 0);

        k_argmin<<<HALF_BLOCKS, 128>>>(z, emb_w, out, HALF_BLOCKS);
        cudaEventRecord(g_ss.evB, 0);
        cudaStreamWaitEvent(g_ss.s2, g_ss.evB, 0);
        k_onehot<<<OH_HALF_BLOCKS, 256, 0, g_ss.s2>>>(out, N_TOK / 2);
        cudaEventRecord(g_ss.evJ, g_ss.s2);

        // serial chain overlaps onehot(half1)
        k_stats<<<1, 1024>>>(ema_cs, out);
        k_emb<<<(N_E * E_DIM + 255) / 256, 256>>>(ema_w);
        k_zq<<<ZQ_BLOCKS, 256>>>(z, out);

        cudaStreamWaitEvent(0, g_ss.evJ, 0);
    } else {
        k_argmin<<<HALF_BLOCKS, 128>>>(z, emb_w, out, 0);
        k_argmin<<<HALF_BLOCKS, 128>>>(z, emb_w, out, HALF_BLOCKS);
        k_onehot<<<OH_HALF_BLOCKS, 256>>>(out, 0);
        k_onehot<<<OH_HALF_BLOCKS, 256>>>(out, N_TOK / 2);
        k_stats<<<1, 1024>>>(ema_cs, out);
        k_emb<<<(N_E * E_DIM + 255) / 256, 256>>>(ema_w);
        k_zq<<<ZQ_BLOCKS, 256>>>(z, out);
    }
}

// round 13
// speedup vs baseline: 1.7309x; 1.7309x over previous
#include <cuda_runtime.h>
#include <cuda_bf16.h>
#include <math.h>

// Problem constants
#define N_TOK   32768      // 32 * 32 * 32
#define N_E     1024
#define E_DIM   64
#define N_ELEM  2097152    // 32*64*32*32
#define HW      1024
#define BETA    0.25f
#define DECAY   0.99f
#define EPSF    1e-5f

// Output layout (flattened reference tuple, float32)
#define O_LOSS   0
#define O_ZQ     1
#define O_PERP   (1 + N_ELEM)
#define O_MINENC (2 + N_ELEM)
#define O_IDX    (2 + N_ELEM + (size_t)N_TOK*N_E)

// Scratch (no allocations allowed -> device globals)
__device__ int   g_idx[N_TOK];
__device__ float g_enorm[N_E];
__device__ float g_cs[N_E];
__device__ float g_sum[N_E * E_DIM];
__device__ float g_emb[N_E * E_DIM];
__device__ float g_loss_acc;
__device__ unsigned int g_done;

// ---- packed f32x2 helpers (semantics identical to 2x scalar FFMA per lane) ----
#define FMA2(d, a, b, c) \
    asm("fma.rn.f32x2 %0, %1, %2, %3;" : "=l"(d) : "l"(a), "l"(b), "l"(c))
#define UNPACK2(lo, hi, v) \
    asm("mov.b64 {%0, %1}, %2;" : "=f"(lo), "=f"(hi) : "l"(v))
#define PACK2(v, lo, hi) \
    asm("mov.b64 %0, {%1, %2};" : "=l"(v) : "f"(lo), "f"(hi))
#define LDSV2(e01, e23, base, OFF) \
    asm("ld.shared.v2.u64 {%0, %1}, [%2+" #OFF "];" \
        : "=l"(e01), "=l"(e23) : "r"(base))

// ---------------------------------------------------------------------------
// Kernel 0: codebook norms + zero scratch
// ---------------------------------------------------------------------------
__global__ void k_prep(const float* __restrict__ emb) {
    int j = blockIdx.x * 256 + threadIdx.x;
    if (j < N_E) {
        const float* e = emb + j * E_DIM;
        float s0 = 0.f, s1 = 0.f, s2 = 0.f, s3 = 0.f;
        #pragma unroll
        for (int c = 0; c < E_DIM; c += 4) {
            s0 = __fmaf_rn(e[c+0], e[c+0], s0);
            s1 = __fmaf_rn(e[c+1], e[c+1], s1);
            s2 = __fmaf_rn(e[c+2], e[c+2], s2);
            s3 = __fmaf_rn(e[c+3], e[c+3], s3);
        }
        g_enorm[j] = __fadd_rn(__fadd_rn(s0, s1), __fadd_rn(s2, s3));
        g_cs[j] = 0.f;
        float4 z4 = make_float4(0.f, 0.f, 0.f, 0.f);
        float4* s = reinterpret_cast<float4*>(g_sum + j * E_DIM);
        #pragma unroll
        for (int c = 0; c < E_DIM / 4; ++c) s[c] = z4;
        if (j == 0) { g_loss_acc = 0.f; g_done = 0u; }
    }
}

// ---------------------------------------------------------------------------
// Kernel 1: per-token argmin (bit-identical math + config to the 231.5us run:
// single launch, 256 blocks, launch_bounds(128,2))
// ---------------------------------------------------------------------------
#define ST 68

__global__ __launch_bounds__(128, 2)
void k_argmin(const float* __restrict__ z,
              const float* __restrict__ emb,
              float* __restrict__ out) {
    __shared__ __align__(16) float tile[64 * ST];
    __shared__ float sn[64];

    const int t   = threadIdx.x;
    const int n0  = blockIdx.x * 128;
    const int b   = n0 >> 10;
    const int hw0 = n0 & 1023;
    const float* zb = z + (size_t)b * E_DIM * HW;

    float4 zr[16];
    #pragma unroll
    for (int g = 0; g < 2; ++g) {
        __syncthreads();
        #pragma unroll
        for (int k = 0; k < 32; ++k) {
            int c = k * 2 + (t >> 6);
            int i = t & 63;
            tile[i * ST + c] = zb[c * HW + hw0 + g * 64 + i];
        }
        __syncthreads();
        if ((t >> 6) == g) {
            int local = t & 63;
            #pragma unroll
            for (int q = 0; q < 16; ++q)
                zr[q] = *reinterpret_cast<const float4*>(&tile[local * ST + 4 * q]);
        }
    }

    unsigned long long zp[32];
    #pragma unroll
    for (int q = 0; q < 16; ++q) {
        PACK2(zp[2*q+0], zr[q].x, zr[q].y);
        PACK2(zp[2*q+1], zr[q].z, zr[q].w);
    }

    float zn;
    {
        unsigned long long na = 0ull, nb = 0ull;
        #pragma unroll
        for (int q = 0; q < 16; ++q) {
            FMA2(na, zp[2*q+0], zp[2*q+0], na);
            FMA2(nb, zp[2*q+1], zp[2*q+1], nb);
        }
        float a0, a1, a2, a3;
        UNPACK2(a0, a1, na);
        UNPACK2(a2, a3, nb);
        zn = __fadd_rn(__fadd_rn(a0, a1), __fadd_rn(a2, a3));
    }

    float best = 3.4e38f;
    int bestIdx = 0;
    const unsigned tbase = (unsigned)__cvta_generic_to_shared(tile);

    for (int tile0 = 0; tile0 < N_E; tile0 += 64) {
        __syncthreads();
        #pragma unroll
        for (int k = 0; k < 32; ++k) {
            int j = k * 2 + (t >> 6);
            int c = t & 63;
            tile[j * ST + c] = emb[(tile0 + j) * E_DIM + c];
        }
        if (t < 64) sn[t] = g_enorm[tile0 + t];
        __syncthreads();

        #pragma unroll 4
        for (int j = 0; j < 64; ++j) {
            const unsigned rowa = tbase + (unsigned)(j * (ST * 4));
            unsigned long long acc_a = 0ull, acc_b = 0ull;
            unsigned long long e01, e23;
            LDSV2(e01, e23, rowa,   0); FMA2(acc_a, zp[ 0], e01, acc_a); FMA2(acc_b, zp[ 1], e23, acc_b);
            LDSV2(e01, e23, rowa,  16); FMA2(acc_a, zp[ 2], e01, acc_a); FMA2(acc_b, zp[ 3], e23, acc_b);
            LDSV2(e01, e23, rowa,  32); FMA2(acc_a, zp[ 4], e01, acc_a); FMA2(acc_b, zp[ 5], e23, acc_b);
            LDSV2(e01, e23, rowa,  48); FMA2(acc_a, zp[ 6], e01, acc_a); FMA2(acc_b, zp[ 7], e23, acc_b);
            LDSV2(e01, e23, rowa,  64); FMA2(acc_a, zp[ 8], e01, acc_a); FMA2(acc_b, zp[ 9], e23, acc_b);
            LDSV2(e01, e23, rowa,  80); FMA2(acc_a, zp[10], e01, acc_a); FMA2(acc_b, zp[11], e23, acc_b);
            LDSV2(e01, e23, rowa,  96); FMA2(acc_a, zp[12], e01, acc_a); FMA2(acc_b, zp[13], e23, acc_b);
            LDSV2(e01, e23, rowa, 112); FMA2(acc_a, zp[14], e01, acc_a); FMA2(acc_b, zp[15], e23, acc_b);
            LDSV2(e01, e23, rowa, 128); FMA2(acc_a, zp[16], e01, acc_a); FMA2(acc_b, zp[17], e23, acc_b);
            LDSV2(e01, e23, rowa, 144); FMA2(acc_a, zp[18], e01, acc_a); FMA2(acc_b, zp[19], e23, acc_b);
            LDSV2(e01, e23, rowa, 160); FMA2(acc_a, zp[20], e01, acc_a); FMA2(acc_b, zp[21], e23, acc_b);
            LDSV2(e01, e23, rowa, 176); FMA2(acc_a, zp[22], e01, acc_a); FMA2(acc_b, zp[23], e23, acc_b);
            LDSV2(e01, e23, rowa, 192); FMA2(acc_a, zp[24], e01, acc_a); FMA2(acc_b, zp[25], e23, acc_b);
            LDSV2(e01, e23, rowa, 208); FMA2(acc_a, zp[26], e01, acc_a); FMA2(acc_b, zp[27], e23, acc_b);
            LDSV2(e01, e23, rowa, 224); FMA2(acc_a, zp[28], e01, acc_a); FMA2(acc_b, zp[29], e23, acc_b);
            LDSV2(e01, e23, rowa, 240); FMA2(acc_a, zp[30], e01, acc_a); FMA2(acc_b, zp[31], e23, acc_b);

            float d0, d1, d2, d3;
            UNPACK2(d0, d1, acc_a);
            UNPACK2(d2, d3, acc_b);
            float dot = __fadd_rn(__fadd_rn(d0, d1), __fadd_rn(d2, d3));
            float dval = __fadd_rn(__fadd_rn(zn, sn[j]), -__fmul_rn(2.0f, dot));
            if (dval < best) { best = dval; bestIdx = tile0 + j; }
        }
    }

    const int n = n0 + t;
    g_idx[n] = bestIdx;
    out[O_IDX + n] = (float)bestIdx;

    atomicAdd(&g_cs[bestIdx], 1.0f);
    float* s = g_sum + bestIdx * E_DIM;
    #pragma unroll
    for (int q = 0; q < 32; ++q) {
        float lo, hi;
        UNPACK2(lo, hi, zp[q]);
        atomicAdd(&s[2*q+0], lo);
        atomicAdd(&s[2*q+1], hi);
    }
}

// ---------------------------------------------------------------------------
// Kernel 2: fused stats + codebook EMA update (+ perplexity in block 0).
// Every block redundantly computes nsum from the 1024 L2-resident cluster
// sizes (identical deterministic order across blocks) -> no single-block
// serialization node.
// ---------------------------------------------------------------------------
__global__ __launch_bounds__(256)
void k_statsemb(const float* __restrict__ ema_cs,
                const float* __restrict__ ema_w,
                float* __restrict__ out) {
    __shared__ float red[256];
    const int tid = threadIdx.x;
    const float KD = (float)(1.0 - 0.99);

    // nsum = sum over 1024 ncs (grouped-4 per thread, then tree)
    float local = 0.f;
    #pragma unroll
    for (int k = 0; k < 4; ++k) {
        int j = tid * 4 + k;
        float ncs = __fadd_rn(__fmul_rn(DECAY, ema_cs[j]),
                              __fmul_rn(KD, g_cs[j]));
        local = __fadd_rn(local, ncs);
    }
    red[tid] = local;
    __syncthreads();
    for (int s = 128; s > 0; s >>= 1) {
        if (tid < s) red[tid] = __fadd_rn(red[tid], red[tid + s]);
        __syncthreads();
    }
    const float nsum = red[0];
    __syncthreads();

    // this block's 256 codebook elements
    int i = blockIdx.x * 256 + tid;     // 0..65535
    int j = i >> 6;
    float ncs = __fadd_rn(__fmul_rn(DECAY, ema_cs[j]),
                          __fmul_rn(KD, g_cs[j]));
    float csn = __fmul_rn(__fdiv_rn(__fadd_rn(ncs, EPSF),
                                    __fadd_rn(nsum, (float)N_E * EPSF)), nsum);
    float nw = __fadd_rn(__fmul_rn(DECAY, ema_w[i]),
                         __fmul_rn(KD, g_sum[i]));
    g_emb[i] = __fdiv_rn(nw, csn);

    // perplexity (block 0 only)
    if (blockIdx.x == 0) {
        float p = 0.f;
        #pragma unroll
        for (int k = 0; k < 4; ++k) {
            int jj = tid * 4 + k;
            float avg = g_cs[jj] * (1.0f / (float)N_TOK);
            p = __fadd_rn(p, __fmul_rn(avg, logf(__fadd_rn(avg, 1e-10f))));
        }
        red[tid] = p;
        __syncthreads();
        for (int s = 128; s > 0; s >>= 1) {
            if (tid < s) red[tid] = __fadd_rn(red[tid], red[tid + s]);
            __syncthreads();
        }
        if (tid == 0) out[O_PERP] = expf(-red[0]);
    }
}

// ---------------------------------------------------------------------------
// Kernel 3: fused z_q/loss + one-hot in ONE launch (block-index split) so the
// two DRAM streams overlap without relying on stream forks.
// ---------------------------------------------------------------------------
#define ZQ_BLOCKS (N_ELEM / 256)            // 8192
#define OH_BLOCKS (N_TOK * (N_E / 2) / 256) // 65536

__global__ __launch_bounds__(256)
void k_zq_onehot(const float* __restrict__ z, float* __restrict__ out) {
    if (blockIdx.x < ZQ_BLOCKS) {
        __shared__ float warpsum[8];
        int i = blockIdx.x * 256 + threadIdx.x;
        int hw = i & 1023;
        int c  = (i >> 10) & 63;
        int b  = i >> 16;
        int n  = (b << 10) | hw;
        float q  = g_emb[g_idx[n] * E_DIM + c];
        float zv = z[i];
        float dq = __fsub_rn(q, zv);
        out[O_ZQ + i] = __fadd_rn(zv, dq);
        float acc = __fmul_rn(dq, dq);
        #pragma unroll
        for (int s = 16; s > 0; s >>= 1)
            acc += __shfl_down_sync(0xffffffffu, acc, s);
        int lane = threadIdx.x & 31, wid = threadIdx.x >> 5;
        if (lane == 0) warpsum[wid] = acc;
        __syncthreads();
        if (wid == 0) {
            float v = (lane < 8) ? warpsum[lane] : 0.f;
            #pragma unroll
            for (int s = 4; s > 0; s >>= 1)
                v += __shfl_down_sync(0xffffffffu, v, s);
            if (lane == 0) {
                atomicAdd(&g_loss_acc, v);
                __threadfence();
                unsigned int done = atomicAdd(&g_done, 1u);
                if (done == ZQ_BLOCKS - 1) {
                    out[O_LOSS] = __fmul_rn(BETA,
                                            __fdiv_rn(g_loss_acc, (float)N_ELEM));
                }
            }
        }
    } else {
        int i = (blockIdx.x - ZQ_BLOCKS) * 256 + threadIdx.x;  // float2 index
        int n = i >> 9;
        int c = (i & 511) << 1;
        int idx = g_idx[n];
        float2 v;
        v.x = (c     == idx) ? 1.0f : 0.0f;
        v.y = (c + 1 == idx) ? 1.0f : 0.0f;
        reinterpret_cast<float2*>(out + O_MINENC)[i] = v;
    }
}

// ---------------------------------------------------------------------------
extern "C" void kernel_launch(void* const* d_in, const int* in_sizes, int n_in,
                              void* d_out, int out_size) {
    const float* z      = (const float*)d_in[0];
    const float* emb_w  = (const float*)d_in[1];
    const float* ema_cs = (const float*)d_in[2];
    const float* ema_w  = (const float*)d_in[3];
    float* out = (float*)d_out;

    k_prep<<<(N_E + 255) / 256, 256>>>(emb_w);
    k_argmin<<<N_TOK / 128, 128>>>(z, emb_w, out);
    k_statsemb<<<(N_E * E_DIM) / 256, 256>>>(ema_cs, ema_w, out);
    k_zq_onehot<<<ZQ_BLOCKS + OH_BLOCKS, 256>>>(z, out);
}

// round 14
// speedup vs baseline: 1.9490x; 1.1260x over previous
#include <cuda_runtime.h>
#include <cuda_bf16.h>
#include <math.h>

// Problem constants
#define N_TOK   32768      // 32 * 32 * 32
#define N_E     1024
#define E_DIM   64
#define N_ELEM  2097152    // 32*64*32*32
#define HW      1024
#define BETA    0.25f
#define DECAY   0.99f
#define EPSF    1e-5f

// Output layout (flattened reference tuple, float32)
#define O_LOSS   0
#define O_ZQ     1
#define O_PERP   (1 + N_ELEM)
#define O_MINENC (2 + N_ELEM)
#define O_IDX    (2 + N_ELEM + (size_t)N_TOK*N_E)

// Scratch (no allocations allowed -> device globals)
__device__ int   g_idx[N_TOK];
__device__ float g_enorm[N_E];
__device__ float g_cs[N_E];
__device__ float g_sum[N_E * E_DIM];
__device__ float g_emb[N_E * E_DIM];
__device__ float g_loss_acc;
__device__ unsigned int g_done;

// ---- packed f32x2 helpers (semantics identical to 2x scalar FFMA per lane) ----
#define FMA2(d, a, b, c) \
    asm("fma.rn.f32x2 %0, %1, %2, %3;" : "=l"(d) : "l"(a), "l"(b), "l"(c))
#define UNPACK2(lo, hi, v) \
    asm("mov.b64 {%0, %1}, %2;" : "=f"(lo), "=f"(hi) : "l"(v))
#define PACK2(v, lo, hi) \
    asm("mov.b64 %0, {%1, %2};" : "=l"(v) : "f"(lo), "f"(hi))
#define LDSV2(e01, e23, base, OFF) \
    asm("ld.shared.v2.u64 {%0, %1}, [%2+" #OFF "];" \
        : "=l"(e01), "=l"(e23) : "r"(base))

// ---------------------------------------------------------------------------
// Kernel 0: codebook norms + zero scratch
// ---------------------------------------------------------------------------
__global__ void k_prep(const float* __restrict__ emb) {
    int j = blockIdx.x * 256 + threadIdx.x;
    if (j < N_E) {
        const float* e = emb + j * E_DIM;
        float s0 = 0.f, s1 = 0.f, s2 = 0.f, s3 = 0.f;
        #pragma unroll
        for (int c = 0; c < E_DIM; c += 4) {
            s0 = __fmaf_rn(e[c+0], e[c+0], s0);
            s1 = __fmaf_rn(e[c+1], e[c+1], s1);
            s2 = __fmaf_rn(e[c+2], e[c+2], s2);
            s3 = __fmaf_rn(e[c+3], e[c+3], s3);
        }
        g_enorm[j] = __fadd_rn(__fadd_rn(s0, s1), __fadd_rn(s2, s3));
        g_cs[j] = 0.f;
        float4 z4 = make_float4(0.f, 0.f, 0.f, 0.f);
        float4* s = reinterpret_cast<float4*>(g_sum + j * E_DIM);
        #pragma unroll
        for (int c = 0; c < E_DIM / 4; ++c) s[c] = z4;
        if (j == 0) { g_loss_acc = 0.f; g_done = 0u; }
    }
}

// ---------------------------------------------------------------------------
// Kernel 1: per-token argmin (bit-identical to the passing 231.5/228.4 kernel)
// ---------------------------------------------------------------------------
#define ST 68

__global__ __launch_bounds__(128, 2)
void k_argmin(const float* __restrict__ z,
              const float* __restrict__ emb,
              float* __restrict__ out) {
    __shared__ __align__(16) float tile[64 * ST];
    __shared__ float sn[64];

    const int t   = threadIdx.x;
    const int n0  = blockIdx.x * 128;
    const int b   = n0 >> 10;
    const int hw0 = n0 & 1023;
    const float* zb = z + (size_t)b * E_DIM * HW;

    float4 zr[16];
    #pragma unroll
    for (int g = 0; g < 2; ++g) {
        __syncthreads();
        #pragma unroll
        for (int k = 0; k < 32; ++k) {
            int c = k * 2 + (t >> 6);
            int i = t & 63;
            tile[i * ST + c] = zb[c * HW + hw0 + g * 64 + i];
        }
        __syncthreads();
        if ((t >> 6) == g) {
            int local = t & 63;
            #pragma unroll
            for (int q = 0; q < 16; ++q)
                zr[q] = *reinterpret_cast<const float4*>(&tile[local * ST + 4 * q]);
        }
    }

    unsigned long long zp[32];
    #pragma unroll
    for (int q = 0; q < 16; ++q) {
        PACK2(zp[2*q+0], zr[q].x, zr[q].y);
        PACK2(zp[2*q+1], zr[q].z, zr[q].w);
    }

    float zn;
    {
        unsigned long long na = 0ull, nb = 0ull;
        #pragma unroll
        for (int q = 0; q < 16; ++q) {
            FMA2(na, zp[2*q+0], zp[2*q+0], na);
            FMA2(nb, zp[2*q+1], zp[2*q+1], nb);
        }
        float a0, a1, a2, a3;
        UNPACK2(a0, a1, na);
        UNPACK2(a2, a3, nb);
        zn = __fadd_rn(__fadd_rn(a0, a1), __fadd_rn(a2, a3));
    }

    float best = 3.4e38f;
    int bestIdx = 0;
    const unsigned tbase = (unsigned)__cvta_generic_to_shared(tile);

    for (int tile0 = 0; tile0 < N_E; tile0 += 64) {
        __syncthreads();
        #pragma unroll
        for (int k = 0; k < 32; ++k) {
            int j = k * 2 + (t >> 6);
            int c = t & 63;
            tile[j * ST + c] = emb[(tile0 + j) * E_DIM + c];
        }
        if (t < 64) sn[t] = g_enorm[tile0 + t];
        __syncthreads();

        #pragma unroll 4
        for (int j = 0; j < 64; ++j) {
            const unsigned rowa = tbase + (unsigned)(j * (ST * 4));
            unsigned long long acc_a = 0ull, acc_b = 0ull;
            unsigned long long e01, e23;
            LDSV2(e01, e23, rowa,   0); FMA2(acc_a, zp[ 0], e01, acc_a); FMA2(acc_b, zp[ 1], e23, acc_b);
            LDSV2(e01, e23, rowa,  16); FMA2(acc_a, zp[ 2], e01, acc_a); FMA2(acc_b, zp[ 3], e23, acc_b);
            LDSV2(e01, e23, rowa,  32); FMA2(acc_a, zp[ 4], e01, acc_a); FMA2(acc_b, zp[ 5], e23, acc_b);
            LDSV2(e01, e23, rowa,  48); FMA2(acc_a, zp[ 6], e01, acc_a); FMA2(acc_b, zp[ 7], e23, acc_b);
            LDSV2(e01, e23, rowa,  64); FMA2(acc_a, zp[ 8], e01, acc_a); FMA2(acc_b, zp[ 9], e23, acc_b);
            LDSV2(e01, e23, rowa,  80); FMA2(acc_a, zp[10], e01, acc_a); FMA2(acc_b, zp[11], e23, acc_b);
            LDSV2(e01, e23, rowa,  96); FMA2(acc_a, zp[12], e01, acc_a); FMA2(acc_b, zp[13], e23, acc_b);
            LDSV2(e01, e23, rowa, 112); FMA2(acc_a, zp[14], e01, acc_a); FMA2(acc_b, zp[15], e23, acc_b);
            LDSV2(e01, e23, rowa, 128); FMA2(acc_a, zp[16], e01, acc_a); FMA2(acc_b, zp[17], e23, acc_b);
            LDSV2(e01, e23, rowa, 144); FMA2(acc_a, zp[18], e01, acc_a); FMA2(acc_b, zp[19], e23, acc_b);
            LDSV2(e01, e23, rowa, 160); FMA2(acc_a, zp[20], e01, acc_a); FMA2(acc_b, zp[21], e23, acc_b);
            LDSV2(e01, e23, rowa, 176); FMA2(acc_a, zp[22], e01, acc_a); FMA2(acc_b, zp[23], e23, acc_b);
            LDSV2(e01, e23, rowa, 192); FMA2(acc_a, zp[24], e01, acc_a); FMA2(acc_b, zp[25], e23, acc_b);
            LDSV2(e01, e23, rowa, 208); FMA2(acc_a, zp[26], e01, acc_a); FMA2(acc_b, zp[27], e23, acc_b);
            LDSV2(e01, e23, rowa, 224); FMA2(acc_a, zp[28], e01, acc_a); FMA2(acc_b, zp[29], e23, acc_b);
            LDSV2(e01, e23, rowa, 240); FMA2(acc_a, zp[30], e01, acc_a); FMA2(acc_b, zp[31], e23, acc_b);

            float d0, d1, d2, d3;
            UNPACK2(d0, d1, acc_a);
            UNPACK2(d2, d3, acc_b);
            float dot = __fadd_rn(__fadd_rn(d0, d1), __fadd_rn(d2, d3));
            float dval = __fadd_rn(__fadd_rn(zn, sn[j]), -__fmul_rn(2.0f, dot));
            if (dval < best) { best = dval; bestIdx = tile0 + j; }
        }
    }

    const int n = n0 + t;
    g_idx[n] = bestIdx;
    out[O_IDX + n] = (float)bestIdx;

    atomicAdd(&g_cs[bestIdx], 1.0f);
    float* s = g_sum + bestIdx * E_DIM;
    #pragma unroll
    for (int q = 0; q < 32; ++q) {
        float lo, hi;
        UNPACK2(lo, hi, zp[q]);
        atomicAdd(&s[2*q+0], lo);
        atomicAdd(&s[2*q+1], hi);
    }
}

// ---------------------------------------------------------------------------
// Kernel 2: fused stats + codebook EMA update (+ perplexity in block 0)
// ---------------------------------------------------------------------------
__global__ __launch_bounds__(256)
void k_statsemb(const float* __restrict__ ema_cs,
                const float* __restrict__ ema_w,
                float* __restrict__ out) {
    __shared__ float red[256];
    const int tid = threadIdx.x;
    const float KD = (float)(1.0 - 0.99);

    float local = 0.f;
    #pragma unroll
    for (int k = 0; k < 4; ++k) {
        int j = tid * 4 + k;
        float ncs = __fadd_rn(__fmul_rn(DECAY, ema_cs[j]),
                              __fmul_rn(KD, g_cs[j]));
        local = __fadd_rn(local, ncs);
    }
    red[tid] = local;
    __syncthreads();
    for (int s = 128; s > 0; s >>= 1) {
        if (tid < s) red[tid] = __fadd_rn(red[tid], red[tid + s]);
        __syncthreads();
    }
    const float nsum = red[0];
    __syncthreads();

    int i = blockIdx.x * 256 + tid;
    int j = i >> 6;
    float ncs = __fadd_rn(__fmul_rn(DECAY, ema_cs[j]),
                          __fmul_rn(KD, g_cs[j]));
    float csn = __fmul_rn(__fdiv_rn(__fadd_rn(ncs, EPSF),
                                    __fadd_rn(nsum, (float)N_E * EPSF)), nsum);
    float nw = __fadd_rn(__fmul_rn(DECAY, ema_w[i]),
                         __fmul_rn(KD, g_sum[i]));
    g_emb[i] = __fdiv_rn(nw, csn);

    if (blockIdx.x == 0) {
        float p = 0.f;
        #pragma unroll
        for (int k = 0; k < 4; ++k) {
            int jj = tid * 4 + k;
            float avg = g_cs[jj] * (1.0f / (float)N_TOK);
            p = __fadd_rn(p, __fmul_rn(avg, logf(__fadd_rn(avg, 1e-10f))));
        }
        red[tid] = p;
        __syncthreads();
        for (int s = 128; s > 0; s >>= 1) {
            if (tid < s) red[tid] = __fadd_rn(red[tid], red[tid + s]);
            __syncthreads();
        }
        if (tid == 0) out[O_PERP] = expf(-red[0]);
    }
}

// ---------------------------------------------------------------------------
// Kernel 3: fused z_q/loss + one-hot, ONE launch, high per-thread MLP.
//   zq side:     1024 blocks, 8 elems/thread (stride-256 coalesced)
//   onehot side: 8192 blocks, 4 rows/block, 8 float2 stores/thread,
//                each iteration writes a contiguous 2KB chunk
// ---------------------------------------------------------------------------
#define ZQB  (N_ELEM / 2048)        // 1024 zq blocks
#define OHB  (N_TOK / 4)            // 8192 onehot blocks

__global__ __launch_bounds__(256)
void k_zq_onehot(const float* __restrict__ z, float* __restrict__ out) {
    const int tid = threadIdx.x;
    if (blockIdx.x < ZQB) {
        __shared__ float warpsum[8];
        int base = blockIdx.x * 2048 + tid;
        float acc = 0.f;
        #pragma unroll
        for (int k = 0; k < 8; ++k) {
            int i = base + k * 256;
            int hw = i & 1023;
            int c  = (i >> 10) & 63;
            int b  = i >> 16;
            int n  = (b << 10) | hw;
            float q  = g_emb[g_idx[n] * E_DIM + c];
            float zv = z[i];
            float dq = __fsub_rn(q, zv);
            out[O_ZQ + i] = __fadd_rn(zv, dq);
            acc = __fadd_rn(acc, __fmul_rn(dq, dq));
        }
        #pragma unroll
        for (int s = 16; s > 0; s >>= 1)
            acc += __shfl_down_sync(0xffffffffu, acc, s);
        int lane = tid & 31, wid = tid >> 5;
        if (lane == 0) warpsum[wid] = acc;
        __syncthreads();
        if (wid == 0) {
            float v = (lane < 8) ? warpsum[lane] : 0.f;
            #pragma unroll
            for (int s = 4; s > 0; s >>= 1)
                v += __shfl_down_sync(0xffffffffu, v, s);
            if (lane == 0) {
                atomicAdd(&g_loss_acc, v);
                __threadfence();
                unsigned int done = atomicAdd(&g_done, 1u);
                if (done == ZQB - 1) {
                    out[O_LOSS] = __fmul_rn(BETA,
                                            __fdiv_rn(g_loss_acc, (float)N_ELEM));
                }
            }
        }
    } else {
        int blk = blockIdx.x - ZQB;
        int n0 = blk * 4;                         // 4 tokens per block
        int i0 = g_idx[n0+0], i1 = g_idx[n0+1], i2 = g_idx[n0+2], i3 = g_idx[n0+3];
        float2* dst = reinterpret_cast<float2*>(out + O_MINENC) + (size_t)n0 * 512;
        #pragma unroll
        for (int it = 0; it < 8; ++it) {
            int row  = it >> 1;                   // 0..3
            int idx  = (row == 0) ? i0 : (row == 1) ? i1 : (row == 2) ? i2 : i3;
            int pos  = ((it & 1) << 8) + tid;     // 0..511 within row
            int c    = pos << 1;
            float2 v;
            v.x = (c     == idx) ? 1.0f : 0.0f;
            v.y = (c + 1 == idx) ? 1.0f : 0.0f;
            dst[row * 512 + pos] = v;
        }
    }
}

// ---------------------------------------------------------------------------
extern "C" void kernel_launch(void* const* d_in, const int* in_sizes, int n_in,
                              void* d_out, int out_size) {
    const float* z      = (const float*)d_in[0];
    const float* emb_w  = (const float*)d_in[1];
    const float* ema_cs = (const float*)d_in[2];
    const float* ema_w  = (const float*)d_in[3];
    float* out = (float*)d_out;

    k_prep<<<(N_E + 255) / 256, 256>>>(emb_w);
    k_argmin<<<N_TOK / 128, 128>>>(z, emb_w, out);
    k_statsemb<<<(N_E * E_DIM) / 256, 256>>>(ema_cs, ema_w, out);
    k_zq_onehot<<<ZQB + OHB, 256>>>(z, out);
}